// round 14
// baseline (speedup 1.0000x reference)
#include <cuda_runtime.h>
#include <cuda_fp16.h>
#include <cmath>
#include <cstdint>

typedef unsigned int u32;
typedef unsigned long long u64;

#define NPTS   131072
#define TMASK  524287u
#define NLVL   24
#define ODIM   896
#define MTILES 1024
#define HTILES 512          // tiles per half

// ---------------------------------------------------------------------------
// Scratch: row-major fp16 activations (single) + fp16 hi/lo weights [N,K]
// ---------------------------------------------------------------------------
__device__ __align__(128) __half g_X [25165824];   // 131072 x 192
__device__ __align__(128) __half g_H1[33554432];   // 131072 x 256
__device__ __align__(128) __half g_H2[33554432];
__device__ __align__(128) __half g_D1[33554432];   // dino hidden
__device__ __align__(128) __half g_Whi[524288];
__device__ __align__(128) __half g_Wlo[524288];

// weight layout (converted, [N,K] row-major, concatenated):
// [cin 256x192][din 256x192][h0 256x256][h1][h2][cout 512x256][dout 384x256]
#define W_IN   0          // combined 512x192
#define W_H    98304
#define W_COUT 294912
#define W_DOUT 425984

struct ResArr { float r[NLVL]; };

// ---------------------------------------------------------------------------
__device__ __forceinline__ u32 swz(u32 b) { return b ^ ((b >> 3) & 0x70); }

__device__ __forceinline__ u32 smem_u32(const void* p) {
    u32 a;
    asm("{ .reg .u64 t; cvta.to.shared.u64 t, %1; cvt.u32.u64 %0, t; }"
        : "=r"(a) : "l"(p));
    return a;
}

__device__ __forceinline__ void cpa16(u32 dst, const void* src) {
    asm volatile("cp.async.cg.shared.global [%0], [%1], 16;" :: "r"(dst), "l"(src));
}

#define LDSM4(R, ADDR) \
    asm volatile("ldmatrix.sync.aligned.m8n8.x4.shared.b16 {%0,%1,%2,%3}, [%4];" \
        : "=r"((R)[0]), "=r"((R)[1]), "=r"((R)[2]), "=r"((R)[3]) : "r"(ADDR))

#define MMA16816(D, A, B) \
    asm volatile("mma.sync.aligned.m16n8k16.row.col.f32.f16.f16.f32 " \
        "{%0,%1,%2,%3},{%4,%5,%6,%7},{%8,%9},{%0,%1,%2,%3};" \
        : "+f"((D)[0]), "+f"((D)[1]), "+f"((D)[2]), "+f"((D)[3]) \
        : "r"((A)[0]), "r"((A)[1]), "r"((A)[2]), "r"((A)[3]), \
          "r"((B)[0]), "r"((B)[1]))

__device__ __forceinline__ u32 pack2h(float a, float b) {
    __half2 h = __floats2half2_rn(a, b);
    return *(u32*)&h;
}

// ---------------------------------------------------------------------------
// Weight conversion: 7 matrices -> fp16 hi/lo [N,K] concat
// ---------------------------------------------------------------------------
__global__ __launch_bounds__(256) void convert_all_w(
    const float* cin, const float* ch, const float* cout,
    const float* din, const float* dout,
    __half* __restrict__ hi, __half* __restrict__ lo)
{
    const float* srcs[7] = {cin, din, ch, ch + 65536, ch + 131072, cout, dout};
    const int   Ks[7]    = {192, 192, 256, 256, 256, 256, 256};
    const int   Ns[7]    = {256, 256, 256, 256, 256, 512, 384};

    for (int id = blockIdx.x * 256 + threadIdx.x; id < 524288; id += gridDim.x * 256) {
        int base = 0, j = -1, rel = 0;
        #pragma unroll
        for (int t = 0; t < 7; t++) {
            int sz = Ks[t] * Ns[t];
            if (j < 0 && id < base + sz) { j = t; rel = id - base; }
            base += sz;
        }
        int K = Ks[j], N = Ns[j];
        int n = rel / K, k = rel % K;
        float v = srcs[j][(size_t)k * N + n];
        __half h = __float2half(v);
        __half l = __float2half(v - __half2float(h));
        hi[id] = h;
        lo[id] = l;
    }
}

// ---------------------------------------------------------------------------
// Hash-grid encode: paired-lane gather (R9-proven), fp16 output, tile offset.
// ---------------------------------------------------------------------------
__global__ __launch_bounds__(256) void encode_kernel(
    const float* __restrict__ pos,
    const float* __restrict__ table0,
    const float* __restrict__ table1,
    __half* __restrict__ xout, ResArr rp, int tbase)
{
    extern __shared__ char sm[];
    int tid  = threadIdx.x;
    int warp = tid >> 5, lane = tid & 31;
    int pp = lane >> 1, h = lane & 1;
    int row = warp * 16 + pp;                 // 0..127
    int bx = blockIdx.x + tbase;
    int i = bx * 128 + row;

    float px = pos[3 * i + 0];
    float py = pos[3 * i + 1];
    float pz = pos[3 * i + 2];
    float mag = sqrtf(px * px + py * py + pz * pz);
    if (mag >= 1.0f) {
        float inv = 1.0f / mag;
        float s = (2.0f - inv) * inv;
        px *= s; py *= s; pz *= s;
    }
    px = (px + 2.0f) * 0.25f;
    py = (py + 2.0f) * 0.25f;
    pz = (pz + 2.0f) * 0.25f;

    #pragma unroll 1
    for (int l = 0; l < NLVL; l++) {
        const float* tab = (l < 12)
            ? (table0 + (size_t)l        * ((size_t)524288 * 8))
            : (table1 + (size_t)(l - 12) * ((size_t)524288 * 8));
        float res = rp.r[l];
        float x = px * res, y = py * res, z = pz * res;
        float fx = floorf(x), fy = floorf(y), fz = floorf(z);
        float wx = x - fx, wy = y - fy, wz = z - fz;
        unsigned x0 = (unsigned)fx, y0 = (unsigned)fy, z0 = (unsigned)fz;

        float f0 = 0.f, f1 = 0.f, f2 = 0.f, f3 = 0.f;
        #pragma unroll
        for (int c = 0; c < 8; c++) {
            unsigned cx = x0 + ((c >> 2) & 1);
            unsigned cy = y0 + ((c >> 1) & 1);
            unsigned cz = z0 + (c & 1);
            unsigned hh = cx ^ (cy * 2654435761u) ^ (cz * 805459861u);
            unsigned idx = hh & TMASK;
            float w = ((c & 4) ? wx : 1.0f - wx)
                    * ((c & 2) ? wy : 1.0f - wy)
                    * ((c & 1) ? wz : 1.0f - wz);
            float4 v = __ldg((const float4*)(tab + (size_t)idx * 8) + h);
            f0 += w * v.x; f1 += w * v.y; f2 += w * v.z; f3 += w * v.w;
        }
        u32 off = (u32)row * 384 + (u32)l * 16 + (u32)h * 8;
        *(u32*)(sm + off)     = pack2h(f0, f1);
        *(u32*)(sm + off + 4) = pack2h(f2, f3);
    }
    __syncthreads();

    const float4* sh = (const float4*)sm;
    float4* dh = (float4*)(xout + (size_t)bx * 128 * 192);
    #pragma unroll
    for (int j = 0; j < 12; j++)
        dh[tid + j * 256] = sh[tid + j * 256];
}

// ---------------------------------------------------------------------------
// fp16 HMMA GEMM: D = A * (Whi + Wlo)^T, 2-term. Row-tile offset ybase.
// BK=64, 2-stage pipeline (96KB smem), 2 CTA/SM, one barrier per chunk.
// ---------------------------------------------------------------------------
template <int EPI>
__global__ __launch_bounds__(256, 2) void gemm_mma(
    const __half* __restrict__ A,
    const __half* __restrict__ Bhi, const __half* __restrict__ Blo,
    int K, int N, int ybase,
    __half* __restrict__ O, __half* __restrict__ O2, int splitx,
    float* __restrict__ Of, int ldc, int colbase)
{
    extern __shared__ char sm[];
    u32 smb = smem_u32(sm);
    int tid = threadIdx.x;
    int lane = tid & 31;
    int warp = tid >> 5;
    int wr = warp & 3;
    int wc = warp >> 2;
    int kcn = K >> 6;                       // BK = 64
    int by = blockIdx.y + ybase;

    const char* aP = (const char*)A   + (size_t)by * 128 * K * 2;
    const char* bH = (const char*)Bhi + (size_t)blockIdx.x * 128 * K * 2;
    const char* bL = (const char*)Blo + (size_t)blockIdx.x * 128 * K * 2;
    u32 rowK2 = (u32)K * 2;

    auto load_chunk = [&](int c, int buf) {
        u32 base = smb + buf * 49152;
        u32 srcb = (u32)c * 128;            // 64 fp16 = 128B
        #pragma unroll
        for (int i = 0; i < 12; i++) {
            u32 q = tid + i * 256;          // 0..3071
            u32 sel = q >> 10;              // 0:A 1:Bhi 2:Blo
            u32 u = q & 1023;
            u32 row = u >> 3, c16 = (u & 7) * 16;
            u32 d = base + sel * 16384 + swz(row * 128 + c16);
            const char* s = (sel == 0) ? aP : (sel == 1) ? bH : bL;
            cpa16(d, s + row * rowK2 + srcb + c16);
        }
        asm volatile("cp.async.commit_group;");
    };

    float acc[2][8][4];
    #pragma unroll
    for (int m = 0; m < 2; m++)
        #pragma unroll
        for (int n = 0; n < 8; n++)
            #pragma unroll
            for (int j = 0; j < 4; j++) acc[m][n][j] = 0.f;

    load_chunk(0, 0);

    u32 aRowB = (u32)(wr * 32 + (lane & 15)) * 128;
    u32 aColB = (u32)((lane >> 4) << 4);
    u32 bRowB = (u32)(wc * 64 + ((lane >> 4) << 3) + (lane & 7)) * 128;
    u32 bColB = (u32)(((lane >> 3) & 1) << 4);

    for (int c = 0; c < kcn; c++) {
        asm volatile("cp.async.wait_group 0;");
        __syncthreads();
        if (c + 1 < kcn) load_chunk(c + 1, (c + 1) & 1);

        u32 base = smb + (c & 1) * 49152;
        #pragma unroll
        for (int ks = 0; ks < 4; ks++) {
            u32 ah[2][4];
            #pragma unroll
            for (int m = 0; m < 2; m++)
                LDSM4(ah[m], base + swz(aRowB + (u32)m * 2048 + (u32)ks * 32 + aColB));
            u32 bh[4][4], bl[4][4];
            #pragma unroll
            for (int nb = 0; nb < 4; nb++) {
                u32 r = bRowB + (u32)nb * 2048 + (u32)ks * 32 + bColB;
                LDSM4(bh[nb], base + 16384 + swz(r));
                LDSM4(bl[nb], base + 32768 + swz(r));
            }
            #pragma unroll
            for (int n8 = 0; n8 < 8; n8++) {
                u32* fh = &bh[n8 >> 1][(n8 & 1) * 2];
                u32* fl = &bl[n8 >> 1][(n8 & 1) * 2];
                MMA16816(acc[0][n8], ah[0], fh);
                MMA16816(acc[1][n8], ah[1], fh);
                MMA16816(acc[0][n8], ah[0], fl);
                MMA16816(acc[1][n8], ah[1], fl);
            }
        }
    }

    if (EPI == 1) {
        bool second = (int)blockIdx.x >= splitx;
        __half* o = second ? O2 : O;
        int bxl = second ? blockIdx.x - splitx : blockIdx.x;
        int rbase = by * 128 + wr * 32 + (lane >> 2);
        int cbase = bxl * 128 + wc * 64 + (lane & 3) * 2;
        #pragma unroll
        for (int m = 0; m < 2; m++)
            #pragma unroll
            for (int n8 = 0; n8 < 8; n8++) {
                int col = cbase + n8 * 8;
                #pragma unroll
                for (int h = 0; h < 2; h++) {
                    size_t row = (size_t)(rbase + m * 16 + h * 8);
                    float a = fmaxf(acc[m][n8][2 * h], 0.f);
                    float b = fmaxf(acc[m][n8][2 * h + 1], 0.f);
                    *(u32*)(o + row * N + col) = pack2h(a, b);
                }
            }
    } else {
        int rbase = by * 128 + wr * 32 + (lane >> 2);
        int cbase = blockIdx.x * 128 + wc * 64 + (lane & 3) * 2;
        #pragma unroll
        for (int m = 0; m < 2; m++)
            #pragma unroll
            for (int n8 = 0; n8 < 8; n8++) {
                int col = colbase + cbase + n8 * 8;
                #pragma unroll
                for (int h = 0; h < 2; h++) {
                    size_t row = (size_t)(rbase + m * 16 + h * 8);
                    float2 v = make_float2(acc[m][n8][2 * h], acc[m][n8][2 * h + 1]);
                    *(float2*)(Of + row * ldc + col) = v;
                }
            }
    }
}

// ---------------------------------------------------------------------------
__global__ __launch_bounds__(128) void normalize_clip(float* __restrict__ out, int rbase)
{
    float* p = out + (size_t)(blockIdx.x + rbase) * ODIM;
    int t = threadIdx.x;
    float v0 = p[t]       + 1e-8f;
    float v1 = p[t + 128] + 1e-8f;
    float v2 = p[t + 256] + 1e-8f;
    float v3 = p[t + 384] + 1e-8f;
    float ss = v0 * v0 + v1 * v1 + v2 * v2 + v3 * v3;
    #pragma unroll
    for (int o = 16; o > 0; o >>= 1)
        ss += __shfl_xor_sync(0xffffffffu, ss, o);
    __shared__ float ws[4];
    if ((t & 31) == 0) ws[t >> 5] = ss;
    __syncthreads();
    float tot = ws[0] + ws[1] + ws[2] + ws[3];
    float denom = fmaxf(sqrtf(tot), 1e-4f);
    p[t]       = v0 / denom;
    p[t + 128] = v1 / denom;
    p[t + 256] = v2 / denom;
    p[t + 384] = v3 / denom;
}

// ---------------------------------------------------------------------------
static void compute_resolutions(ResArr* rp)
{
    const double starts[2] = {16.0, 128.0};
    const double ends[2]   = {128.0, 512.0};
    for (int h = 0; h < 2; h++) {
        double growth = exp((log(ends[h]) - log(starts[h])) / 11.0);
        for (int k = 0; k < 12; k++)
            rp->r[h * 12 + k] = (float)floor(starts[h] * pow(growth, (double)k));
    }
}

extern "C" void kernel_launch(void* const* d_in, const int* in_sizes, int n_in,
                              void* d_out, int out_size)
{
    const float* positions  = (const float*)d_in[0];
    const float* table0     = (const float*)d_in[1];
    const float* table1     = (const float*)d_in[2];
    const float* clip_w_in  = (const float*)d_in[3];
    const float* clip_w_h   = (const float*)d_in[4];
    const float* clip_w_out = (const float*)d_in[5];
    const float* dino_w_in  = (const float*)d_in[6];
    const float* dino_w_out = (const float*)d_in[7];
    float* out = (float*)d_out;

    __half *X, *H1, *H2, *D1, *Whi, *Wlo;
    cudaGetSymbolAddress((void**)&X,   g_X);
    cudaGetSymbolAddress((void**)&H1,  g_H1);
    cudaGetSymbolAddress((void**)&H2,  g_H2);
    cudaGetSymbolAddress((void**)&D1,  g_D1);
    cudaGetSymbolAddress((void**)&Whi, g_Whi);
    cudaGetSymbolAddress((void**)&Wlo, g_Wlo);

    cudaFuncSetAttribute(encode_kernel, cudaFuncAttributeMaxDynamicSharedMemorySize, 49152);
    cudaFuncSetAttribute(gemm_mma<1>, cudaFuncAttributeMaxDynamicSharedMemorySize, 98304);
    cudaFuncSetAttribute(gemm_mma<0>, cudaFuncAttributeMaxDynamicSharedMemorySize, 98304);

    ResArr rp;
    compute_resolutions(&rp);

    static cudaStream_t sB = nullptr, sD = nullptr;
    static cudaEvent_t evF = nullptr, evW = nullptr, evE0 = nullptr,
                       evL0 = nullptr, evL1 = nullptr, evB = nullptr, evD = nullptr;
    if (!sB) {
        cudaStreamCreateWithFlags(&sB, cudaStreamNonBlocking);
        cudaStreamCreateWithFlags(&sD, cudaStreamNonBlocking);
        cudaEventCreateWithFlags(&evF,  cudaEventDisableTiming);
        cudaEventCreateWithFlags(&evW,  cudaEventDisableTiming);
        cudaEventCreateWithFlags(&evE0, cudaEventDisableTiming);
        cudaEventCreateWithFlags(&evL0, cudaEventDisableTiming);
        cudaEventCreateWithFlags(&evL1, cudaEventDisableTiming);
        cudaEventCreateWithFlags(&evB,  cudaEventDisableTiming);
        cudaEventCreateWithFlags(&evD,  cudaEventDisableTiming);
    }

    const int SMEM = 98304;

    // FORK: both side streams must originate from the capturing stream.
    cudaEventRecord(evF, 0);
    cudaStreamWaitEvent(sB, evF, 0);
    cudaStreamWaitEvent(sD, evF, 0);

    // weights on sB (finishes in ~6us)
    convert_all_w<<<512, 256, 0, sB>>>(clip_w_in, clip_w_h, clip_w_out,
                                       dino_w_in, dino_w_out, Whi, Wlo);
    cudaEventRecord(evW, sB);

    // half 0 encode on stream 0
    encode_kernel<<<HTILES, 256, 49152>>>(positions, table0, table1, X, rp, 0);
    cudaEventRecord(evE0, 0);

    // half 1 encode on sB AFTER enc0 (so it overlaps chain0, not enc0)
    cudaStreamWaitEvent(sB, evE0, 0);
    encode_kernel<<<HTILES, 256, 49152, sB>>>(positions, table0, table1, X, rp, HTILES);

    // ---- chain 0 (stream 0, rows 0..65535) ----
    cudaStreamWaitEvent(0, evW, 0);
    gemm_mma<1><<<dim3(4, HTILES), 256, SMEM>>>(X, Whi + W_IN, Wlo + W_IN,
                                                192, 256, 0, H1, D1, 2, nullptr, 0, 0);
    cudaEventRecord(evL0, 0);
    gemm_mma<1><<<dim3(2, HTILES), 256, SMEM>>>(H1, Whi + W_H, Wlo + W_H,
                                                256, 256, 0, H2, nullptr, 8, nullptr, 0, 0);
    gemm_mma<1><<<dim3(2, HTILES), 256, SMEM>>>(H2, Whi + W_H + 65536, Wlo + W_H + 65536,
                                                256, 256, 0, H1, nullptr, 8, nullptr, 0, 0);
    gemm_mma<1><<<dim3(2, HTILES), 256, SMEM>>>(H1, Whi + W_H + 131072, Wlo + W_H + 131072,
                                                256, 256, 0, H2, nullptr, 8, nullptr, 0, 0);
    gemm_mma<0><<<dim3(4, HTILES), 256, SMEM>>>(H2, Whi + W_COUT, Wlo + W_COUT,
                                                256, 0, 0, nullptr, nullptr, 8,
                                                out, ODIM, 0);
    normalize_clip<<<NPTS / 2, 128>>>(out, 0);

    // ---- chain 1 (sB, rows 65536..131071) ----
    gemm_mma<1><<<dim3(4, HTILES), 256, SMEM, sB>>>(X, Whi + W_IN, Wlo + W_IN,
                                                    192, 256, HTILES, H1, D1, 2, nullptr, 0, 0);
    cudaEventRecord(evL1, sB);
    gemm_mma<1><<<dim3(2, HTILES), 256, SMEM, sB>>>(H1, Whi + W_H, Wlo + W_H,
                                                    256, 256, HTILES, H2, nullptr, 8, nullptr, 0, 0);
    gemm_mma<1><<<dim3(2, HTILES), 256, SMEM, sB>>>(H2, Whi + W_H + 65536, Wlo + W_H + 65536,
                                                    256, 256, HTILES, H1, nullptr, 8, nullptr, 0, 0);
    gemm_mma<1><<<dim3(2, HTILES), 256, SMEM, sB>>>(H1, Whi + W_H + 131072, Wlo + W_H + 131072,
                                                    256, 256, HTILES, H2, nullptr, 8, nullptr, 0, 0);
    gemm_mma<0><<<dim3(4, HTILES), 256, SMEM, sB>>>(H2, Whi + W_COUT, Wlo + W_COUT,
                                                    256, 0, HTILES, nullptr, nullptr, 8,
                                                    out, ODIM, 0);
    normalize_clip<<<NPTS / 2, 128, 0, sB>>>(out, NPTS / 2);
    cudaEventRecord(evB, sB);

    // ---- dino heads on sD, forked off each half's L1 ----
    cudaStreamWaitEvent(sD, evL0, 0);
    gemm_mma<0><<<dim3(3, HTILES), 256, SMEM, sD>>>(D1, Whi + W_DOUT, Wlo + W_DOUT,
                                                    256, 0, 0, nullptr, nullptr, 8,
                                                    out, ODIM, 512);
    cudaStreamWaitEvent(sD, evL1, 0);
    gemm_mma<0><<<dim3(3, HTILES), 256, SMEM, sD>>>(D1, Whi + W_DOUT, Wlo + W_DOUT,
                                                    256, 0, HTILES, nullptr, nullptr, 8,
                                                    out, ODIM, 512);
    cudaEventRecord(evD, sD);

    // join everything on stream 0
    cudaStreamWaitEvent(0, evB, 0);
    cudaStreamWaitEvent(0, evD, 0);
}

// round 15
// speedup vs baseline: 1.1128x; 1.1128x over previous
#include <cuda_runtime.h>
#include <cuda_fp16.h>
#include <cmath>
#include <cstdint>

typedef unsigned int u32;
typedef unsigned long long u64;

#define NPTS   131072
#define TMASK  524287u
#define NLVL   24
#define ODIM   896
#define MTILES 1024
#define HTILES 512          // tiles per half

// ---------------------------------------------------------------------------
// Scratch: row-major fp16 activations (single) + fp16 hi/lo weights [N,K]
// ---------------------------------------------------------------------------
__device__ __align__(128) __half g_X [25165824];   // 131072 x 192
__device__ __align__(128) __half g_H1[33554432];   // 131072 x 256
__device__ __align__(128) __half g_H2[33554432];
__device__ __align__(128) __half g_D1[33554432];   // dino hidden
__device__ __align__(128) __half g_Whi[524288];
__device__ __align__(128) __half g_Wlo[524288];

// weight layout (converted, [N,K] row-major, concatenated):
// [cin 256x192][din 256x192][h0 256x256][h1][h2][cout 512x256][dout 384x256]
#define W_IN   0          // combined 512x192
#define W_H    98304
#define W_COUT 294912
#define W_DOUT 425984

struct ResArr { float r[NLVL]; };

// ---------------------------------------------------------------------------
__device__ __forceinline__ u32 swz(u32 b) { return b ^ ((b >> 3) & 0x70); }

__device__ __forceinline__ u32 smem_u32(const void* p) {
    u32 a;
    asm("{ .reg .u64 t; cvta.to.shared.u64 t, %1; cvt.u32.u64 %0, t; }"
        : "=r"(a) : "l"(p));
    return a;
}

__device__ __forceinline__ void cpa16(u32 dst, const void* src) {
    asm volatile("cp.async.cg.shared.global [%0], [%1], 16;" :: "r"(dst), "l"(src));
}

#define LDSM4(R, ADDR) \
    asm volatile("ldmatrix.sync.aligned.m8n8.x4.shared.b16 {%0,%1,%2,%3}, [%4];" \
        : "=r"((R)[0]), "=r"((R)[1]), "=r"((R)[2]), "=r"((R)[3]) : "r"(ADDR))

#define MMA16816(D, A, B) \
    asm volatile("mma.sync.aligned.m16n8k16.row.col.f32.f16.f16.f32 " \
        "{%0,%1,%2,%3},{%4,%5,%6,%7},{%8,%9},{%0,%1,%2,%3};" \
        : "+f"((D)[0]), "+f"((D)[1]), "+f"((D)[2]), "+f"((D)[3]) \
        : "r"((A)[0]), "r"((A)[1]), "r"((A)[2]), "r"((A)[3]), \
          "r"((B)[0]), "r"((B)[1]))

__device__ __forceinline__ u32 pack2h(float a, float b) {
    __half2 h = __floats2half2_rn(a, b);
    return *(u32*)&h;
}

// ---------------------------------------------------------------------------
// Weight conversion: 7 matrices -> fp16 hi/lo [N,K] concat
// ---------------------------------------------------------------------------
__global__ __launch_bounds__(256) void convert_all_w(
    const float* cin, const float* ch, const float* cout,
    const float* din, const float* dout,
    __half* __restrict__ hi, __half* __restrict__ lo)
{
    const float* srcs[7] = {cin, din, ch, ch + 65536, ch + 131072, cout, dout};
    const int   Ks[7]    = {192, 192, 256, 256, 256, 256, 256};
    const int   Ns[7]    = {256, 256, 256, 256, 256, 512, 384};

    for (int id = blockIdx.x * 256 + threadIdx.x; id < 524288; id += gridDim.x * 256) {
        int base = 0, j = -1, rel = 0;
        #pragma unroll
        for (int t = 0; t < 7; t++) {
            int sz = Ks[t] * Ns[t];
            if (j < 0 && id < base + sz) { j = t; rel = id - base; }
            base += sz;
        }
        int K = Ks[j], N = Ns[j];
        int n = rel / K, k = rel % K;
        float v = srcs[j][(size_t)k * N + n];
        __half h = __float2half(v);
        __half l = __float2half(v - __half2float(h));
        hi[id] = h;
        lo[id] = l;
    }
}

// ---------------------------------------------------------------------------
// Hash-grid encode: paired-lane gather (R9-proven), fp16 output, tile offset.
// ---------------------------------------------------------------------------
__global__ __launch_bounds__(256) void encode_kernel(
    const float* __restrict__ pos,
    const float* __restrict__ table0,
    const float* __restrict__ table1,
    __half* __restrict__ xout, ResArr rp, int tbase)
{
    extern __shared__ char sm[];
    int tid  = threadIdx.x;
    int warp = tid >> 5, lane = tid & 31;
    int pp = lane >> 1, h = lane & 1;
    int row = warp * 16 + pp;                 // 0..127
    int bx = blockIdx.x + tbase;
    int i = bx * 128 + row;

    float px = pos[3 * i + 0];
    float py = pos[3 * i + 1];
    float pz = pos[3 * i + 2];
    float mag = sqrtf(px * px + py * py + pz * pz);
    if (mag >= 1.0f) {
        float inv = 1.0f / mag;
        float s = (2.0f - inv) * inv;
        px *= s; py *= s; pz *= s;
    }
    px = (px + 2.0f) * 0.25f;
    py = (py + 2.0f) * 0.25f;
    pz = (pz + 2.0f) * 0.25f;

    #pragma unroll 1
    for (int l = 0; l < NLVL; l++) {
        const float* tab = (l < 12)
            ? (table0 + (size_t)l        * ((size_t)524288 * 8))
            : (table1 + (size_t)(l - 12) * ((size_t)524288 * 8));
        float res = rp.r[l];
        float x = px * res, y = py * res, z = pz * res;
        float fx = floorf(x), fy = floorf(y), fz = floorf(z);
        float wx = x - fx, wy = y - fy, wz = z - fz;
        unsigned x0 = (unsigned)fx, y0 = (unsigned)fy, z0 = (unsigned)fz;

        float f0 = 0.f, f1 = 0.f, f2 = 0.f, f3 = 0.f;
        #pragma unroll
        for (int c = 0; c < 8; c++) {
            unsigned cx = x0 + ((c >> 2) & 1);
            unsigned cy = y0 + ((c >> 1) & 1);
            unsigned cz = z0 + (c & 1);
            unsigned hh = cx ^ (cy * 2654435761u) ^ (cz * 805459861u);
            unsigned idx = hh & TMASK;
            float w = ((c & 4) ? wx : 1.0f - wx)
                    * ((c & 2) ? wy : 1.0f - wy)
                    * ((c & 1) ? wz : 1.0f - wz);
            float4 v = __ldg((const float4*)(tab + (size_t)idx * 8) + h);
            f0 += w * v.x; f1 += w * v.y; f2 += w * v.z; f3 += w * v.w;
        }
        u32 off = (u32)row * 384 + (u32)l * 16 + (u32)h * 8;
        *(u32*)(sm + off)     = pack2h(f0, f1);
        *(u32*)(sm + off + 4) = pack2h(f2, f3);
    }
    __syncthreads();

    const float4* sh = (const float4*)sm;
    float4* dh = (float4*)(xout + (size_t)bx * 128 * 192);
    #pragma unroll
    for (int j = 0; j < 12; j++)
        dh[tid + j * 256] = sh[tid + j * 256];
}

// ---------------------------------------------------------------------------
// fp16 HMMA GEMM: D = A * W^T.
// TERMS=2: W = Whi + Wlo (hi/lo split).  TERMS=1: W = Whi only (heads).
// BK=64, 2-stage pipeline (96KB smem), 2 CTA/SM, one barrier per chunk.
// EPI 1: relu + fp16 out (splitx routing). EPI 0: fp32 into d_out.
// ---------------------------------------------------------------------------
template <int EPI, int TERMS>
__global__ __launch_bounds__(256, 2) void gemm_mma(
    const __half* __restrict__ A,
    const __half* __restrict__ Bhi, const __half* __restrict__ Blo,
    int K, int N, int ybase,
    __half* __restrict__ O, __half* __restrict__ O2, int splitx,
    float* __restrict__ Of, int ldc, int colbase)
{
    extern __shared__ char sm[];
    u32 smb = smem_u32(sm);
    int tid = threadIdx.x;
    int lane = tid & 31;
    int warp = tid >> 5;
    int wr = warp & 3;
    int wc = warp >> 2;
    int kcn = K >> 6;                       // BK = 64
    int by = blockIdx.y + ybase;

    const char* aP = (const char*)A   + (size_t)by * 128 * K * 2;
    const char* bH = (const char*)Bhi + (size_t)blockIdx.x * 128 * K * 2;
    const char* bL = (const char*)Blo + (size_t)blockIdx.x * 128 * K * 2;
    u32 rowK2 = (u32)K * 2;

    auto load_chunk = [&](int c, int buf) {
        u32 base = smb + buf * 49152;
        u32 srcb = (u32)c * 128;            // 64 fp16 = 128B
        const int NSEC = (TERMS == 2) ? 12 : 8;   // A+Bhi+Blo or A+Bhi
        #pragma unroll
        for (int i = 0; i < NSEC; i++) {
            u32 q = tid + i * 256;
            u32 sel = q >> 10;              // 0:A 1:Bhi 2:Blo
            u32 u = q & 1023;
            u32 row = u >> 3, c16 = (u & 7) * 16;
            u32 d = base + sel * 16384 + swz(row * 128 + c16);
            const char* s = (sel == 0) ? aP : (sel == 1) ? bH : bL;
            cpa16(d, s + row * rowK2 + srcb + c16);
        }
        asm volatile("cp.async.commit_group;");
    };

    float acc[2][8][4];
    #pragma unroll
    for (int m = 0; m < 2; m++)
        #pragma unroll
        for (int n = 0; n < 8; n++)
            #pragma unroll
            for (int j = 0; j < 4; j++) acc[m][n][j] = 0.f;

    load_chunk(0, 0);

    u32 aRowB = (u32)(wr * 32 + (lane & 15)) * 128;
    u32 aColB = (u32)((lane >> 4) << 4);
    u32 bRowB = (u32)(wc * 64 + ((lane >> 4) << 3) + (lane & 7)) * 128;
    u32 bColB = (u32)(((lane >> 3) & 1) << 4);

    for (int c = 0; c < kcn; c++) {
        asm volatile("cp.async.wait_group 0;");
        __syncthreads();
        if (c + 1 < kcn) load_chunk(c + 1, (c + 1) & 1);

        u32 base = smb + (c & 1) * 49152;
        #pragma unroll
        for (int ks = 0; ks < 4; ks++) {
            u32 ah[2][4];
            #pragma unroll
            for (int m = 0; m < 2; m++)
                LDSM4(ah[m], base + swz(aRowB + (u32)m * 2048 + (u32)ks * 32 + aColB));
            u32 bh[4][4], bl[4][4];
            #pragma unroll
            for (int nb = 0; nb < 4; nb++) {
                u32 r = bRowB + (u32)nb * 2048 + (u32)ks * 32 + bColB;
                LDSM4(bh[nb], base + 16384 + swz(r));
                if (TERMS == 2) LDSM4(bl[nb], base + 32768 + swz(r));
            }
            #pragma unroll
            for (int n8 = 0; n8 < 8; n8++) {
                u32* fh = &bh[n8 >> 1][(n8 & 1) * 2];
                MMA16816(acc[0][n8], ah[0], fh);
                MMA16816(acc[1][n8], ah[1], fh);
                if (TERMS == 2) {
                    u32* fl = &bl[n8 >> 1][(n8 & 1) * 2];
                    MMA16816(acc[0][n8], ah[0], fl);
                    MMA16816(acc[1][n8], ah[1], fl);
                }
            }
        }
    }

    if (EPI == 1) {
        bool second = (int)blockIdx.x >= splitx;
        __half* o = second ? O2 : O;
        int bxl = second ? blockIdx.x - splitx : blockIdx.x;
        int rbase = by * 128 + wr * 32 + (lane >> 2);
        int cbase = bxl * 128 + wc * 64 + (lane & 3) * 2;
        #pragma unroll
        for (int m = 0; m < 2; m++)
            #pragma unroll
            for (int n8 = 0; n8 < 8; n8++) {
                int col = cbase + n8 * 8;
                #pragma unroll
                for (int h = 0; h < 2; h++) {
                    size_t row = (size_t)(rbase + m * 16 + h * 8);
                    float a = fmaxf(acc[m][n8][2 * h], 0.f);
                    float b = fmaxf(acc[m][n8][2 * h + 1], 0.f);
                    *(u32*)(o + row * N + col) = pack2h(a, b);
                }
            }
    } else {
        int rbase = by * 128 + wr * 32 + (lane >> 2);
        int cbase = blockIdx.x * 128 + wc * 64 + (lane & 3) * 2;
        #pragma unroll
        for (int m = 0; m < 2; m++)
            #pragma unroll
            for (int n8 = 0; n8 < 8; n8++) {
                int col = colbase + cbase + n8 * 8;
                #pragma unroll
                for (int h = 0; h < 2; h++) {
                    size_t row = (size_t)(rbase + m * 16 + h * 8);
                    float2 v = make_float2(acc[m][n8][2 * h], acc[m][n8][2 * h + 1]);
                    *(float2*)(Of + row * ldc + col) = v;
                }
            }
    }
}

// ---------------------------------------------------------------------------
__global__ __launch_bounds__(128) void normalize_clip(float* __restrict__ out, int rbase)
{
    float* p = out + (size_t)(blockIdx.x + rbase) * ODIM;
    int t = threadIdx.x;
    float v0 = p[t]       + 1e-8f;
    float v1 = p[t + 128] + 1e-8f;
    float v2 = p[t + 256] + 1e-8f;
    float v3 = p[t + 384] + 1e-8f;
    float ss = v0 * v0 + v1 * v1 + v2 * v2 + v3 * v3;
    #pragma unroll
    for (int o = 16; o > 0; o >>= 1)
        ss += __shfl_xor_sync(0xffffffffu, ss, o);
    __shared__ float ws[4];
    if ((t & 31) == 0) ws[t >> 5] = ss;
    __syncthreads();
    float tot = ws[0] + ws[1] + ws[2] + ws[3];
    float denom = fmaxf(sqrtf(tot), 1e-4f);
    p[t]       = v0 / denom;
    p[t + 128] = v1 / denom;
    p[t + 256] = v2 / denom;
    p[t + 384] = v3 / denom;
}

// ---------------------------------------------------------------------------
static void compute_resolutions(ResArr* rp)
{
    const double starts[2] = {16.0, 128.0};
    const double ends[2]   = {128.0, 512.0};
    for (int h = 0; h < 2; h++) {
        double growth = exp((log(ends[h]) - log(starts[h])) / 11.0);
        for (int k = 0; k < 12; k++)
            rp->r[h * 12 + k] = (float)floor(starts[h] * pow(growth, (double)k));
    }
}

extern "C" void kernel_launch(void* const* d_in, const int* in_sizes, int n_in,
                              void* d_out, int out_size)
{
    const float* positions  = (const float*)d_in[0];
    const float* table0     = (const float*)d_in[1];
    const float* table1     = (const float*)d_in[2];
    const float* clip_w_in  = (const float*)d_in[3];
    const float* clip_w_h   = (const float*)d_in[4];
    const float* clip_w_out = (const float*)d_in[5];
    const float* dino_w_in  = (const float*)d_in[6];
    const float* dino_w_out = (const float*)d_in[7];
    float* out = (float*)d_out;

    __half *X, *H1, *H2, *D1, *Whi, *Wlo;
    cudaGetSymbolAddress((void**)&X,   g_X);
    cudaGetSymbolAddress((void**)&H1,  g_H1);
    cudaGetSymbolAddress((void**)&H2,  g_H2);
    cudaGetSymbolAddress((void**)&D1,  g_D1);
    cudaGetSymbolAddress((void**)&Whi, g_Whi);
    cudaGetSymbolAddress((void**)&Wlo, g_Wlo);

    cudaFuncSetAttribute(encode_kernel, cudaFuncAttributeMaxDynamicSharedMemorySize, 49152);
    cudaFuncSetAttribute(gemm_mma<1, 2>, cudaFuncAttributeMaxDynamicSharedMemorySize, 98304);
    cudaFuncSetAttribute(gemm_mma<0, 1>, cudaFuncAttributeMaxDynamicSharedMemorySize, 98304);

    ResArr rp;
    compute_resolutions(&rp);

    static cudaStream_t sB = nullptr, sD = nullptr;
    static cudaEvent_t evF = nullptr, evW = nullptr, evE0 = nullptr,
                       evL0 = nullptr, evL1 = nullptr, evB = nullptr, evD = nullptr;
    if (!sB) {
        cudaStreamCreateWithFlags(&sB, cudaStreamNonBlocking);
        cudaStreamCreateWithFlags(&sD, cudaStreamNonBlocking);
        cudaEventCreateWithFlags(&evF,  cudaEventDisableTiming);
        cudaEventCreateWithFlags(&evW,  cudaEventDisableTiming);
        cudaEventCreateWithFlags(&evE0, cudaEventDisableTiming);
        cudaEventCreateWithFlags(&evL0, cudaEventDisableTiming);
        cudaEventCreateWithFlags(&evL1, cudaEventDisableTiming);
        cudaEventCreateWithFlags(&evB,  cudaEventDisableTiming);
        cudaEventCreateWithFlags(&evD,  cudaEventDisableTiming);
    }

    const int SMEM = 98304;

    // FORK: both side streams originate from the capturing stream.
    cudaEventRecord(evF, 0);
    cudaStreamWaitEvent(sB, evF, 0);
    cudaStreamWaitEvent(sD, evF, 0);

    // weights on sB
    convert_all_w<<<512, 256, 0, sB>>>(clip_w_in, clip_w_h, clip_w_out,
                                       dino_w_in, dino_w_out, Whi, Wlo);
    cudaEventRecord(evW, sB);

    // half 0 encode on stream 0
    encode_kernel<<<HTILES, 256, 49152>>>(positions, table0, table1, X, rp, 0);
    cudaEventRecord(evE0, 0);

    // half 1 encode on sB after enc0
    cudaStreamWaitEvent(sB, evE0, 0);
    encode_kernel<<<HTILES, 256, 49152, sB>>>(positions, table0, table1, X, rp, HTILES);

    // ---- chain 0 (stream 0, rows 0..65535) ----
    cudaStreamWaitEvent(0, evW, 0);
    gemm_mma<1, 2><<<dim3(4, HTILES), 256, SMEM>>>(X, Whi + W_IN, Wlo + W_IN,
                                                   192, 256, 0, H1, D1, 2, nullptr, 0, 0);
    cudaEventRecord(evL0, 0);
    gemm_mma<1, 2><<<dim3(2, HTILES), 256, SMEM>>>(H1, Whi + W_H, Wlo + W_H,
                                                   256, 256, 0, H2, nullptr, 8, nullptr, 0, 0);
    gemm_mma<1, 2><<<dim3(2, HTILES), 256, SMEM>>>(H2, Whi + W_H + 65536, Wlo + W_H + 65536,
                                                   256, 256, 0, H1, nullptr, 8, nullptr, 0, 0);
    gemm_mma<1, 2><<<dim3(2, HTILES), 256, SMEM>>>(H1, Whi + W_H + 131072, Wlo + W_H + 131072,
                                                   256, 256, 0, H2, nullptr, 8, nullptr, 0, 0);
    gemm_mma<0, 1><<<dim3(4, HTILES), 256, SMEM>>>(H2, Whi + W_COUT, nullptr,
                                                   256, 0, 0, nullptr, nullptr, 8,
                                                   out, ODIM, 0);
    normalize_clip<<<NPTS / 2, 128>>>(out, 0);

    // ---- chain 1 (sB, rows 65536..131071) ----
    gemm_mma<1, 2><<<dim3(4, HTILES), 256, SMEM, sB>>>(X, Whi + W_IN, Wlo + W_IN,
                                                       192, 256, HTILES, H1, D1, 2, nullptr, 0, 0);
    cudaEventRecord(evL1, sB);
    gemm_mma<1, 2><<<dim3(2, HTILES), 256, SMEM, sB>>>(H1, Whi + W_H, Wlo + W_H,
                                                       256, 256, HTILES, H2, nullptr, 8, nullptr, 0, 0);
    gemm_mma<1, 2><<<dim3(2, HTILES), 256, SMEM, sB>>>(H2, Whi + W_H + 65536, Wlo + W_H + 65536,
                                                       256, 256, HTILES, H1, nullptr, 8, nullptr, 0, 0);
    gemm_mma<1, 2><<<dim3(2, HTILES), 256, SMEM, sB>>>(H1, Whi + W_H + 131072, Wlo + W_H + 131072,
                                                       256, 256, HTILES, H2, nullptr, 8, nullptr, 0, 0);
    gemm_mma<0, 1><<<dim3(4, HTILES), 256, SMEM, sB>>>(H2, Whi + W_COUT, nullptr,
                                                       256, 0, HTILES, nullptr, nullptr, 8,
                                                       out, ODIM, 0);
    normalize_clip<<<NPTS / 2, 128, 0, sB>>>(out, NPTS / 2);
    cudaEventRecord(evB, sB);

    // ---- dino heads on sD, forked off each half's L1 ----
    cudaStreamWaitEvent(sD, evL0, 0);
    gemm_mma<0, 1><<<dim3(3, HTILES), 256, SMEM, sD>>>(D1, Whi + W_DOUT, nullptr,
                                                       256, 0, 0, nullptr, nullptr, 8,
                                                       out, ODIM, 512);
    cudaStreamWaitEvent(sD, evL1, 0);
    gemm_mma<0, 1><<<dim3(3, HTILES), 256, SMEM, sD>>>(D1, Whi + W_DOUT, nullptr,
                                                       256, 0, HTILES, nullptr, nullptr, 8,
                                                       out, ODIM, 512);
    cudaEventRecord(evD, sD);

    // join everything on stream 0
    cudaStreamWaitEvent(0, evB, 0);
    cudaStreamWaitEvent(0, evD, 0);
}

// round 16
// speedup vs baseline: 1.3635x; 1.2253x over previous
#include <cuda_runtime.h>
#include <cuda_fp16.h>
#include <cmath>
#include <cstdint>

typedef unsigned int u32;
typedef unsigned long long u64;

#define NPTS   131072
#define TMASK  524287u
#define NLVL   24
#define ODIM   896
#define MTILES 1024
#define HTILES 512          // tiles per half

// ---------------------------------------------------------------------------
// Scratch: row-major fp16 activations + plain fp16 weights [N,K]
// ---------------------------------------------------------------------------
__device__ __align__(128) __half g_X [25165824];   // 131072 x 192
__device__ __align__(128) __half g_H1[33554432];   // 131072 x 256
__device__ __align__(128) __half g_H2[33554432];
__device__ __align__(128) __half g_D1[33554432];   // dino hidden
__device__ __align__(128) __half g_W [524288];

// weight layout (converted, [N,K] row-major, concatenated):
// [cin 256x192][din 256x192][h0 256x256][h1][h2][cout 512x256][dout 384x256]
#define W_IN   0          // combined 512x192
#define W_H    98304
#define W_COUT 294912
#define W_DOUT 425984

struct ResArr { float r[NLVL]; };

// ---------------------------------------------------------------------------
__device__ __forceinline__ u32 swz(u32 b) { return b ^ ((b >> 3) & 0x70); }

__device__ __forceinline__ u32 smem_u32(const void* p) {
    u32 a;
    asm("{ .reg .u64 t; cvta.to.shared.u64 t, %1; cvt.u32.u64 %0, t; }"
        : "=r"(a) : "l"(p));
    return a;
}

__device__ __forceinline__ void cpa16(u32 dst, const void* src) {
    asm volatile("cp.async.cg.shared.global [%0], [%1], 16;" :: "r"(dst), "l"(src));
}

#define LDSM4(R, ADDR) \
    asm volatile("ldmatrix.sync.aligned.m8n8.x4.shared.b16 {%0,%1,%2,%3}, [%4];" \
        : "=r"((R)[0]), "=r"((R)[1]), "=r"((R)[2]), "=r"((R)[3]) : "r"(ADDR))

#define MMA16816(D, A, B) \
    asm volatile("mma.sync.aligned.m16n8k16.row.col.f32.f16.f16.f32 " \
        "{%0,%1,%2,%3},{%4,%5,%6,%7},{%8,%9},{%0,%1,%2,%3};" \
        : "+f"((D)[0]), "+f"((D)[1]), "+f"((D)[2]), "+f"((D)[3]) \
        : "r"((A)[0]), "r"((A)[1]), "r"((A)[2]), "r"((A)[3]), \
          "r"((B)[0]), "r"((B)[1]))

__device__ __forceinline__ u32 pack2h(float a, float b) {
    __half2 h = __floats2half2_rn(a, b);
    return *(u32*)&h;
}

// ---------------------------------------------------------------------------
// Weight conversion: 7 matrices -> fp16 [N,K] concat
// ---------------------------------------------------------------------------
__global__ __launch_bounds__(256) void convert_all_w(
    const float* cin, const float* ch, const float* cout,
    const float* din, const float* dout,
    __half* __restrict__ w)
{
    const float* srcs[7] = {cin, din, ch, ch + 65536, ch + 131072, cout, dout};
    const int   Ks[7]    = {192, 192, 256, 256, 256, 256, 256};
    const int   Ns[7]    = {256, 256, 256, 256, 256, 512, 384};

    for (int id = blockIdx.x * 256 + threadIdx.x; id < 524288; id += gridDim.x * 256) {
        int base = 0, j = -1, rel = 0;
        #pragma unroll
        for (int t = 0; t < 7; t++) {
            int sz = Ks[t] * Ns[t];
            if (j < 0 && id < base + sz) { j = t; rel = id - base; }
            base += sz;
        }
        int K = Ks[j], N = Ns[j];
        int n = rel / K, k = rel % K;
        w[id] = __float2half(srcs[j][(size_t)k * N + n]);
    }
}

// ---------------------------------------------------------------------------
// Hash-grid encode: paired-lane gather (R9-proven), fp16 output, tile offset.
// ---------------------------------------------------------------------------
__global__ __launch_bounds__(256) void encode_kernel(
    const float* __restrict__ pos,
    const float* __restrict__ table0,
    const float* __restrict__ table1,
    __half* __restrict__ xout, ResArr rp, int tbase)
{
    extern __shared__ char sm[];
    int tid  = threadIdx.x;
    int warp = tid >> 5, lane = tid & 31;
    int pp = lane >> 1, h = lane & 1;
    int row = warp * 16 + pp;                 // 0..127
    int bx = blockIdx.x + tbase;
    int i = bx * 128 + row;

    float px = pos[3 * i + 0];
    float py = pos[3 * i + 1];
    float pz = pos[3 * i + 2];
    float mag = sqrtf(px * px + py * py + pz * pz);
    if (mag >= 1.0f) {
        float inv = 1.0f / mag;
        float s = (2.0f - inv) * inv;
        px *= s; py *= s; pz *= s;
    }
    px = (px + 2.0f) * 0.25f;
    py = (py + 2.0f) * 0.25f;
    pz = (pz + 2.0f) * 0.25f;

    #pragma unroll 1
    for (int l = 0; l < NLVL; l++) {
        const float* tab = (l < 12)
            ? (table0 + (size_t)l        * ((size_t)524288 * 8))
            : (table1 + (size_t)(l - 12) * ((size_t)524288 * 8));
        float res = rp.r[l];
        float x = px * res, y = py * res, z = pz * res;
        float fx = floorf(x), fy = floorf(y), fz = floorf(z);
        float wx = x - fx, wy = y - fy, wz = z - fz;
        unsigned x0 = (unsigned)fx, y0 = (unsigned)fy, z0 = (unsigned)fz;

        float f0 = 0.f, f1 = 0.f, f2 = 0.f, f3 = 0.f;
        #pragma unroll
        for (int c = 0; c < 8; c++) {
            unsigned cx = x0 + ((c >> 2) & 1);
            unsigned cy = y0 + ((c >> 1) & 1);
            unsigned cz = z0 + (c & 1);
            unsigned hh = cx ^ (cy * 2654435761u) ^ (cz * 805459861u);
            unsigned idx = hh & TMASK;
            float w = ((c & 4) ? wx : 1.0f - wx)
                    * ((c & 2) ? wy : 1.0f - wy)
                    * ((c & 1) ? wz : 1.0f - wz);
            float4 v = __ldg((const float4*)(tab + (size_t)idx * 8) + h);
            f0 += w * v.x; f1 += w * v.y; f2 += w * v.z; f3 += w * v.w;
        }
        u32 off = (u32)row * 384 + (u32)l * 16 + (u32)h * 8;
        *(u32*)(sm + off)     = pack2h(f0, f1);
        *(u32*)(sm + off + 4) = pack2h(f2, f3);
    }
    __syncthreads();

    const float4* sh = (const float4*)sm;
    float4* dh = (float4*)(xout + (size_t)bx * 128 * 192);
    #pragma unroll
    for (int j = 0; j < 12; j++)
        dh[tid + j * 256] = sh[tid + j * 256];
}

// ---------------------------------------------------------------------------
// fp16 HMMA GEMM: D = A * W^T (plain fp16 weights).
// BK=64, THREE-stage cp.async pipeline (96KB smem), 2 CTA/SM, 1 barrier/chunk.
// stage = 32KB: A 16KB @0, B 16KB @16384 (128B rows, SW128).
// EPI 1: relu + fp16 out (splitx routing). EPI 0: fp32 into d_out.
// ---------------------------------------------------------------------------
template <int EPI>
__global__ __launch_bounds__(256, 2) void gemm_mma(
    const __half* __restrict__ A, const __half* __restrict__ B,
    int K, int N, int ybase,
    __half* __restrict__ O, __half* __restrict__ O2, int splitx,
    float* __restrict__ Of, int ldc, int colbase)
{
    extern __shared__ char sm[];
    u32 smb = smem_u32(sm);
    int tid = threadIdx.x;
    int lane = tid & 31;
    int warp = tid >> 5;
    int wr = warp & 3;
    int wc = warp >> 2;
    int kcn = K >> 6;                       // BK = 64
    int by = blockIdx.y + ybase;

    const char* aP = (const char*)A + (size_t)by * 128 * K * 2;
    const char* bP = (const char*)B + (size_t)blockIdx.x * 128 * K * 2;
    u32 rowK2 = (u32)K * 2;

    auto load_chunk = [&](int c, int buf) {
        u32 base = smb + buf * 32768;
        u32 srcb = (u32)c * 128;            // 64 fp16 = 128B
        #pragma unroll
        for (int i = 0; i < 8; i++) {
            u32 q = tid + i * 256;          // 0..2047
            u32 sel = q >> 10;              // 0:A 1:B
            u32 u = q & 1023;
            u32 row = u >> 3, c16 = (u & 7) * 16;
            u32 d = base + sel * 16384 + swz(row * 128 + c16);
            const char* s = sel ? bP : aP;
            cpa16(d, s + row * rowK2 + srcb + c16);
        }
        asm volatile("cp.async.commit_group;");
    };

    float acc[2][8][4];
    #pragma unroll
    for (int m = 0; m < 2; m++)
        #pragma unroll
        for (int n = 0; n < 8; n++)
            #pragma unroll
            for (int j = 0; j < 4; j++) acc[m][n][j] = 0.f;

    // prologue: two chunks in flight
    load_chunk(0, 0);
    if (kcn > 1) load_chunk(1, 1);

    u32 aRowB = (u32)(wr * 32 + (lane & 15)) * 128;
    u32 aColB = (u32)((lane >> 4) << 4);
    u32 bRowB = (u32)(wc * 64 + ((lane >> 4) << 3) + (lane & 7)) * 128;
    u32 bColB = (u32)(((lane >> 3) & 1) << 4);

    for (int c = 0; c < kcn; c++) {
        if (c + 1 < kcn) asm volatile("cp.async.wait_group 1;");
        else             asm volatile("cp.async.wait_group 0;");
        __syncthreads();
        if (c + 2 < kcn) load_chunk(c + 2, (c + 2) % 3);

        u32 base = smb + (c % 3) * 32768;
        #pragma unroll
        for (int ks = 0; ks < 4; ks++) {
            u32 ah[2][4];
            #pragma unroll
            for (int m = 0; m < 2; m++)
                LDSM4(ah[m], base + swz(aRowB + (u32)m * 2048 + (u32)ks * 32 + aColB));
            u32 bh[4][4];
            #pragma unroll
            for (int nb = 0; nb < 4; nb++)
                LDSM4(bh[nb], base + 16384 + swz(bRowB + (u32)nb * 2048 + (u32)ks * 32 + bColB));
            #pragma unroll
            for (int n8 = 0; n8 < 8; n8++) {
                u32* fh = &bh[n8 >> 1][(n8 & 1) * 2];
                MMA16816(acc[0][n8], ah[0], fh);
                MMA16816(acc[1][n8], ah[1], fh);
            }
        }
    }

    if (EPI == 1) {
        bool second = (int)blockIdx.x >= splitx;
        __half* o = second ? O2 : O;
        int bxl = second ? blockIdx.x - splitx : blockIdx.x;
        int rbase = by * 128 + wr * 32 + (lane >> 2);
        int cbase = bxl * 128 + wc * 64 + (lane & 3) * 2;
        #pragma unroll
        for (int m = 0; m < 2; m++)
            #pragma unroll
            for (int n8 = 0; n8 < 8; n8++) {
                int col = cbase + n8 * 8;
                #pragma unroll
                for (int h = 0; h < 2; h++) {
                    size_t row = (size_t)(rbase + m * 16 + h * 8);
                    float a = fmaxf(acc[m][n8][2 * h], 0.f);
                    float b = fmaxf(acc[m][n8][2 * h + 1], 0.f);
                    *(u32*)(o + row * N + col) = pack2h(a, b);
                }
            }
    } else {
        int rbase = by * 128 + wr * 32 + (lane >> 2);
        int cbase = blockIdx.x * 128 + wc * 64 + (lane & 3) * 2;
        #pragma unroll
        for (int m = 0; m < 2; m++)
            #pragma unroll
            for (int n8 = 0; n8 < 8; n8++) {
                int col = colbase + cbase + n8 * 8;
                #pragma unroll
                for (int h = 0; h < 2; h++) {
                    size_t row = (size_t)(rbase + m * 16 + h * 8);
                    float2 v = make_float2(acc[m][n8][2 * h], acc[m][n8][2 * h + 1]);
                    *(float2*)(Of + row * ldc + col) = v;
                }
            }
    }
}

// ---------------------------------------------------------------------------
__global__ __launch_bounds__(128) void normalize_clip(float* __restrict__ out, int rbase)
{
    float* p = out + (size_t)(blockIdx.x + rbase) * ODIM;
    int t = threadIdx.x;
    float v0 = p[t]       + 1e-8f;
    float v1 = p[t + 128] + 1e-8f;
    float v2 = p[t + 256] + 1e-8f;
    float v3 = p[t + 384] + 1e-8f;
    float ss = v0 * v0 + v1 * v1 + v2 * v2 + v3 * v3;
    #pragma unroll
    for (int o = 16; o > 0; o >>= 1)
        ss += __shfl_xor_sync(0xffffffffu, ss, o);
    __shared__ float ws[4];
    if ((t & 31) == 0) ws[t >> 5] = ss;
    __syncthreads();
    float tot = ws[0] + ws[1] + ws[2] + ws[3];
    float denom = fmaxf(sqrtf(tot), 1e-4f);
    p[t]       = v0 / denom;
    p[t + 128] = v1 / denom;
    p[t + 256] = v2 / denom;
    p[t + 384] = v3 / denom;
}

// ---------------------------------------------------------------------------
static void compute_resolutions(ResArr* rp)
{
    const double starts[2] = {16.0, 128.0};
    const double ends[2]   = {128.0, 512.0};
    for (int h = 0; h < 2; h++) {
        double growth = exp((log(ends[h]) - log(starts[h])) / 11.0);
        for (int k = 0; k < 12; k++)
            rp->r[h * 12 + k] = (float)floor(starts[h] * pow(growth, (double)k));
    }
}

extern "C" void kernel_launch(void* const* d_in, const int* in_sizes, int n_in,
                              void* d_out, int out_size)
{
    const float* positions  = (const float*)d_in[0];
    const float* table0     = (const float*)d_in[1];
    const float* table1     = (const float*)d_in[2];
    const float* clip_w_in  = (const float*)d_in[3];
    const float* clip_w_h   = (const float*)d_in[4];
    const float* clip_w_out = (const float*)d_in[5];
    const float* dino_w_in  = (const float*)d_in[6];
    const float* dino_w_out = (const float*)d_in[7];
    float* out = (float*)d_out;

    __half *X, *H1, *H2, *D1, *W;
    cudaGetSymbolAddress((void**)&X,  g_X);
    cudaGetSymbolAddress((void**)&H1, g_H1);
    cudaGetSymbolAddress((void**)&H2, g_H2);
    cudaGetSymbolAddress((void**)&D1, g_D1);
    cudaGetSymbolAddress((void**)&W,  g_W);

    cudaFuncSetAttribute(encode_kernel, cudaFuncAttributeMaxDynamicSharedMemorySize, 49152);
    cudaFuncSetAttribute(gemm_mma<1>, cudaFuncAttributeMaxDynamicSharedMemorySize, 98304);
    cudaFuncSetAttribute(gemm_mma<0>, cudaFuncAttributeMaxDynamicSharedMemorySize, 98304);

    ResArr rp;
    compute_resolutions(&rp);

    static cudaStream_t sB = nullptr, sD = nullptr;
    static cudaEvent_t evF = nullptr, evW = nullptr, evE0 = nullptr,
                       evL0 = nullptr, evL1 = nullptr, evB = nullptr, evD = nullptr;
    if (!sB) {
        cudaStreamCreateWithFlags(&sB, cudaStreamNonBlocking);
        cudaStreamCreateWithFlags(&sD, cudaStreamNonBlocking);
        cudaEventCreateWithFlags(&evF,  cudaEventDisableTiming);
        cudaEventCreateWithFlags(&evW,  cudaEventDisableTiming);
        cudaEventCreateWithFlags(&evE0, cudaEventDisableTiming);
        cudaEventCreateWithFlags(&evL0, cudaEventDisableTiming);
        cudaEventCreateWithFlags(&evL1, cudaEventDisableTiming);
        cudaEventCreateWithFlags(&evB,  cudaEventDisableTiming);
        cudaEventCreateWithFlags(&evD,  cudaEventDisableTiming);
    }

    const int SMEM = 98304;

    // FORK: both side streams originate from the capturing stream.
    cudaEventRecord(evF, 0);
    cudaStreamWaitEvent(sB, evF, 0);
    cudaStreamWaitEvent(sD, evF, 0);

    // weights on sB
    convert_all_w<<<512, 256, 0, sB>>>(clip_w_in, clip_w_h, clip_w_out,
                                       dino_w_in, dino_w_out, W);
    cudaEventRecord(evW, sB);

    // half 0 encode on stream 0
    encode_kernel<<<HTILES, 256, 49152>>>(positions, table0, table1, X, rp, 0);
    cudaEventRecord(evE0, 0);

    // half 1 encode on sB after enc0
    cudaStreamWaitEvent(sB, evE0, 0);
    encode_kernel<<<HTILES, 256, 49152, sB>>>(positions, table0, table1, X, rp, HTILES);

    // ---- chain 0 (stream 0, rows 0..65535) ----
    cudaStreamWaitEvent(0, evW, 0);
    gemm_mma<1><<<dim3(4, HTILES), 256, SMEM>>>(X, W + W_IN,
                                                192, 256, 0, H1, D1, 2, nullptr, 0, 0);
    cudaEventRecord(evL0, 0);
    gemm_mma<1><<<dim3(2, HTILES), 256, SMEM>>>(H1, W + W_H,
                                                256, 256, 0, H2, nullptr, 8, nullptr, 0, 0);
    gemm_mma<1><<<dim3(2, HTILES), 256, SMEM>>>(H2, W + W_H + 65536,
                                                256, 256, 0, H1, nullptr, 8, nullptr, 0, 0);
    gemm_mma<1><<<dim3(2, HTILES), 256, SMEM>>>(H1, W + W_H + 131072,
                                                256, 256, 0, H2, nullptr, 8, nullptr, 0, 0);
    gemm_mma<0><<<dim3(4, HTILES), 256, SMEM>>>(H2, W + W_COUT,
                                                256, 0, 0, nullptr, nullptr, 8,
                                                out, ODIM, 0);
    normalize_clip<<<NPTS / 2, 128>>>(out, 0);

    // ---- chain 1 (sB, rows 65536..131071) ----
    gemm_mma<1><<<dim3(4, HTILES), 256, SMEM, sB>>>(X, W + W_IN,
                                                    192, 256, HTILES, H1, D1, 2, nullptr, 0, 0);
    cudaEventRecord(evL1, sB);
    gemm_mma<1><<<dim3(2, HTILES), 256, SMEM, sB>>>(H1, W + W_H,
                                                    256, 256, HTILES, H2, nullptr, 8, nullptr, 0, 0);
    gemm_mma<1><<<dim3(2, HTILES), 256, SMEM, sB>>>(H2, W + W_H + 65536,
                                                    256, 256, HTILES, H1, nullptr, 8, nullptr, 0, 0);
    gemm_mma<1><<<dim3(2, HTILES), 256, SMEM, sB>>>(H1, W + W_H + 131072,
                                                    256, 256, HTILES, H2, nullptr, 8, nullptr, 0, 0);
    gemm_mma<0><<<dim3(4, HTILES), 256, SMEM, sB>>>(H2, W + W_COUT,
                                                    256, 0, HTILES, nullptr, nullptr, 8,
                                                    out, ODIM, 0);
    normalize_clip<<<NPTS / 2, 128, 0, sB>>>(out, NPTS / 2);
    cudaEventRecord(evB, sB);

    // ---- dino heads on sD, forked off each half's L1 ----
    cudaStreamWaitEvent(sD, evL0, 0);
    gemm_mma<0><<<dim3(3, HTILES), 256, SMEM, sD>>>(D1, W + W_DOUT,
                                                    256, 0, 0, nullptr, nullptr, 8,
                                                    out, ODIM, 512);
    cudaStreamWaitEvent(sD, evL1, 0);
    gemm_mma<0><<<dim3(3, HTILES), 256, SMEM, sD>>>(D1, W + W_DOUT,
                                                    256, 0, HTILES, nullptr, nullptr, 8,
                                                    out, ODIM, 512);
    cudaEventRecord(evD, sD);

    // join everything on stream 0
    cudaStreamWaitEvent(0, evB, 0);
    cudaStreamWaitEvent(0, evD, 0);
}